// round 1
// baseline (speedup 1.0000x reference)
#include <cuda_runtime.h>
#include <math_constants.h>
#include <cstdint>

#define BB 8192
#define CC 2048
#define NBINS 32768
#define GAMA 0.3f

// ---------------- scratch (static __device__, no allocs) ----------------
__device__ float g_neg[BB];       // neg[j] = sigmoid(masked rowmax)
__device__ float g_posm[BB];      // m_i = sigmoid(x[i,y_i]) - gamma, +INF if invalid
__device__ float g_sorted[BB];    // neg grouped by bin (counting sort)
__device__ int   g_hist[NBINS];
__device__ int   g_binStart[NBINS + 1];
__device__ int   g_binCursor[NBINS];
__device__ int   g_validCnt;
__device__ int   g_notI64;        // 1 if labels are int32, 0 if int64

__device__ __forceinline__ float sigmoidf_(float v) { return 1.0f / (1.0f + __expf(-v)); }
// Monotonic bin for v in (0,1): float bits are order-preserving for positive floats.
__device__ __forceinline__ int binOf(float v) { return (int)(__float_as_uint(v) >> 15); }

// ---------------- K0: zero scratch ----------------
__global__ void k_zero() {
    int i = blockIdx.x * blockDim.x + threadIdx.x;
    if (i < NBINS) g_hist[i] = 0;
    if (i == 0) { g_validCnt = 0; g_notI64 = 0; }
}

// ---------------- K0b: detect label dtype ----------------
// If y is int64 (values < 2048), the int32 view is [v0,0,v1,0,...]: odd words all 0.
// If y is int32, odd words are real random labels -> some nonzero.
__global__ void k_detect(const int* __restrict__ yw) {
    int i = blockIdx.x * blockDim.x + threadIdx.x;
    if (i < BB && (i & 1) && yw[i] != 0) g_notI64 = 1;
}

// ---------------- K1: per-row masked max + pos, build histogram ----------------
__global__ __launch_bounds__(128) void k_row(const float* __restrict__ x,
                                             const void* __restrict__ yptr) {
    const int row = blockIdx.x;
    const int tid = threadIdx.x;
    int yq;
    if (g_notI64) yq = ((const int*)yptr)[row];
    else          yq = (int)(((const long long*)yptr)[row]);

    const float4* xr = (const float4*)(x + (size_t)row * CC);
    float mx = -CUDART_INF_F;
#pragma unroll 4
    for (int c4 = tid; c4 < CC / 4; c4 += 128) {
        float4 v = __ldg(xr + c4);
        int c = c4 * 4;
        if (c + 0 != 0 && c + 0 != yq) mx = fmaxf(mx, v.x);
        if (c + 1 != yq)               mx = fmaxf(mx, v.y);
        if (c + 2 != yq)               mx = fmaxf(mx, v.z);
        if (c + 3 != yq)               mx = fmaxf(mx, v.w);
    }
#pragma unroll
    for (int o = 16; o; o >>= 1) mx = fmaxf(mx, __shfl_xor_sync(0xffffffffu, mx, o));
    __shared__ float wmax[4];
    if ((tid & 31) == 0) wmax[tid >> 5] = mx;
    __syncthreads();
    if (tid == 0) {
        float m = fmaxf(fmaxf(wmax[0], wmax[1]), fmaxf(wmax[2], wmax[3]));
        float ng = sigmoidf_(m);          // in (0,1); masked fill 0 never wins (sigmoid>0)
        g_neg[row] = ng;
        atomicAdd(&g_hist[binOf(ng)], 1);
        float pm = CUDART_INF_F;
        if (yq != 0) {
            float px = x[(size_t)row * CC + yq];
            pm = sigmoidf_(px) - GAMA;
            atomicAdd(&g_validCnt, 1);
        }
        g_posm[row] = pm;
    }
}

// ---------------- K2: exclusive prefix over bins (1 block) ----------------
__global__ __launch_bounds__(1024) void k_scan() {
    __shared__ int part[1024];
    const int tid = threadIdx.x;
    const int base = tid * 32;                 // 1024*32 = 32768 bins
    int sum = 0;
#pragma unroll
    for (int k = 0; k < 32; k++) sum += g_hist[base + k];
    part[tid] = sum;
    __syncthreads();
    for (int off = 1; off < 1024; off <<= 1) {
        int v = (tid >= off) ? part[tid - off] : 0;
        __syncthreads();
        part[tid] += v;
        __syncthreads();
    }
    int ex = part[tid] - sum;                  // exclusive prefix
#pragma unroll
    for (int k = 0; k < 32; k++) {
        int h = g_hist[base + k];
        g_binStart[base + k]  = ex;
        g_binCursor[base + k] = ex;
        ex += h;
    }
    if (tid == 1023) g_binStart[NBINS] = ex;   // total = BB
}

// ---------------- K3: scatter neg into bin-grouped order ----------------
__global__ void k_scatter() {
    int i = blockIdx.x * blockDim.x + threadIdx.x;
    if (i < BB) {
        float v = g_neg[i];
        int p = atomicAdd(&g_binCursor[binOf(v)], 1);
        g_sorted[p] = v;
    }
}

// ---------------- K4: suffix sums + all queries + final loss (1 block) ----------------
// smem: double sS1[BB+1], sS2[BB+1], p1[1024], p2[1024]; float sneg[BB]
#define K4_SMEM ((size_t)(2 * (BB + 1) + 2 * 1024) * 8 + (size_t)BB * 4)

__global__ __launch_bounds__(1024, 1) void k_main(float* __restrict__ out) {
    extern __shared__ unsigned char smraw[];
    double* sS1 = (double*)smraw;          // BB+1
    double* sS2 = sS1 + (BB + 1);          // BB+1
    double* p1  = sS2 + (BB + 1);          // 1024
    double* p2  = p1 + 1024;               // 1024
    float*  sneg = (float*)(p2 + 1024);    // BB

    const int tid = threadIdx.x;
    for (int i = tid; i < BB; i += 1024) sneg[i] = g_sorted[i];
    __syncthreads();

    // per-thread local suffix over its 8 contiguous elements
    const int base = tid * 8;
    double tl1[8], tl2[8];
    double a1 = 0.0, a2 = 0.0;
#pragma unroll
    for (int k = 7; k >= 0; --k) {
        float n = sneg[base + k];
        a1 += (double)n;
        a2 += (double)n * (double)n;
        tl1[k] = a1; tl2[k] = a2;
    }
    p1[tid] = a1; p2[tid] = a2;
    __syncthreads();
    // inclusive suffix scan of thread totals
    for (int off = 1; off < 1024; off <<= 1) {
        double v1 = (tid + off < 1024) ? p1[tid + off] : 0.0;
        double v2 = (tid + off < 1024) ? p2[tid + off] : 0.0;
        __syncthreads();
        p1[tid] += v1; p2[tid] += v2;
        __syncthreads();
    }
    double o1 = p1[tid] - a1;  // sum strictly after this thread's chunk
    double o2 = p2[tid] - a2;
#pragma unroll
    for (int k = 0; k < 8; k++) { sS1[base + k] = tl1[k] + o1; sS2[base + k] = tl2[k] + o2; }
    if (tid == 0) { sS1[BB] = 0.0; sS2[BB] = 0.0; }
    __syncthreads();

    // queries: sum over i of cnt*m^2 - 2m*S1 + S2 over {neg > m}
    double acc = 0.0;
    for (int i = tid; i < BB; i += 1024) {
        float m = g_posm[i];
        if (!(m < 1.0f)) continue;         // invalid (INF); also m>=1 impossible for neg
        long long cnt; double S1, S2;
        if (m <= 0.0f) {                   // all neg > 0 >= m
            cnt = BB; S1 = sS1[0]; S2 = sS2[0];
        } else {
            int b = binOf(m);
            int st = g_binStart[b], en = g_binStart[b + 1];
            cnt = BB - en; S1 = sS1[en]; S2 = sS2[en];
            for (int t = st; t < en; t++) {      // exact boundary-bin scan
                float n = sneg[t];
                if (n > m) { cnt++; S1 += (double)n; S2 += (double)n * (double)n; }
            }
        }
        double md = (double)m;
        acc += (double)cnt * md * md - 2.0 * md * S1 + S2;
    }
    __syncthreads();
    p1[tid] = acc;
    __syncthreads();
    for (int s = 512; s; s >>= 1) {
        if (tid < s) p1[tid] += p1[tid + s];
        __syncthreads();
    }
    if (tid == 0) {
        double p = (double)g_validCnt;
        double loss = p1[0] / (p + 1.0) / ((double)BB + 1.0);
        out[0] = (float)loss;
    }
}

// ---------------- launch ----------------
extern "C" void kernel_launch(void* const* d_in, const int* in_sizes, int n_in,
                              void* d_out, int out_size) {
    const float* x = (const float*)d_in[0];
    const void*  y = d_in[1];

    k_zero<<<(NBINS + 255) / 256, 256>>>();
    k_detect<<<(BB + 255) / 256, 256>>>((const int*)y);
    k_row<<<BB, 128>>>(x, y);
    k_scan<<<1, 1024>>>();
    k_scatter<<<(BB + 255) / 256, 256>>>();
    cudaFuncSetAttribute(k_main, cudaFuncAttributeMaxDynamicSharedMemorySize, (int)K4_SMEM);
    k_main<<<1, 1024, K4_SMEM>>>((float*)d_out);
}

// round 2
// speedup vs baseline: 3.9730x; 3.9730x over previous
#include <cuda_runtime.h>
#include <math_constants.h>
#include <cstdint>

#define BB 8192
#define CC 2048
#define NBINS 4096
#define GAMA 0.3f

// ---------------- scratch (static __device__, no allocs) ----------------
__device__ float g_neg[BB];       // neg[j] = sigmoid(masked rowmax)
__device__ float g_posm[BB];      // m_i = sigmoid(x[i,y_i]) - gamma, +INF if invalid
__device__ int   g_notI64;        // 1 if labels are int32, 0 if int64

__device__ __forceinline__ float sigmoidf_(float v) { return 1.0f / (1.0f + __expf(-v)); }
// Monotonic bin for v in (0,1): float bits order-preserving for positive floats.
// v < 1.0 -> bits <= 0x3F7FFFFF -> bin <= 2031 < 4096.
__device__ __forceinline__ int binOf(float v) { return (int)(__float_as_uint(v) >> 19); }

// ---------------- K0: detect label dtype (int64 vs int32 view) ----------------
// int64 labels < 2048 -> odd int32 words all zero. int32 labels -> some nonzero.
__global__ __launch_bounds__(1024) void k_detect(const int4* __restrict__ yw) {
    int f = 0;
    for (int i = threadIdx.x; i < BB / 4; i += 1024) {
        int4 v = yw[i];
        f |= (v.y | v.w);
    }
    int any = __syncthreads_or(f);
    if (threadIdx.x == 0) g_notI64 = (any != 0);
}

// ---------------- K1: per-row masked max + pos (HBM-bound, 64 MB) ----------------
__global__ __launch_bounds__(128) void k_row(const float* __restrict__ x,
                                             const void* __restrict__ yptr) {
    const int row = blockIdx.x;
    const int tid = threadIdx.x;
    int yq;
    if (g_notI64) yq = ((const int*)yptr)[row];
    else          yq = (int)(((const long long*)yptr)[row]);

    const float4* xr = (const float4*)(x + (size_t)row * CC);
    float mx = -CUDART_INF_F;
#pragma unroll 4
    for (int c4 = tid; c4 < CC / 4; c4 += 128) {
        float4 v = __ldg(xr + c4);
        int c = c4 * 4;
        if (c + 0 != 0 && c + 0 != yq) mx = fmaxf(mx, v.x);
        if (c + 1 != yq)               mx = fmaxf(mx, v.y);
        if (c + 2 != yq)               mx = fmaxf(mx, v.z);
        if (c + 3 != yq)               mx = fmaxf(mx, v.w);
    }
#pragma unroll
    for (int o = 16; o; o >>= 1) mx = fmaxf(mx, __shfl_xor_sync(0xffffffffu, mx, o));
    __shared__ float wmax[4];
    if ((tid & 31) == 0) wmax[tid >> 5] = mx;
    __syncthreads();
    if (tid == 0) {
        float m = fmaxf(fmaxf(wmax[0], wmax[1]), fmaxf(wmax[2], wmax[3]));
        g_neg[row] = sigmoidf_(m);        // in (0,1); masked fill 0 never wins
        float pm = CUDART_INF_F;
        if (yq != 0) pm = sigmoidf_(x[(size_t)row * CC + yq]) - GAMA;
        g_posm[row] = pm;
    }
}

// ---------------- K2: fused hist + scan + scatter + suffix + queries ----------------
// smem layout (bytes from base):
//   [0      , 65544 )  double sS1[8193]     (transient overlay: float sraw[8192] @0,
//   [65544  , 131088)  double sS2[8193]      int shist[4096] @32768, int scursor[4096] @49152)
//   [131088 , 163856)  float  ssorted[8192]
//   [163856 , 180248)  int    sbinStart[4097] (+pad)
//   [180248 , 188440)  double p1[1024]
//   [188440 , 196632)  double p2[1024]
//   [196632 , 200728)  int    iscan[1024]
#define K2_SMEM 200728

__global__ __launch_bounds__(1024, 1) void k_main(float* __restrict__ out) {
    extern __shared__ unsigned char sm[];
    double* sS1      = (double*)(sm);
    double* sS2      = (double*)(sm + 65544);
    float*  ssorted  = (float*) (sm + 131088);
    int*    sbinStart= (int*)   (sm + 163856);
    double* p1       = (double*)(sm + 180248);
    double* p2       = (double*)(sm + 188440);
    int*    iscan    = (int*)   (sm + 196632);
    // transient overlays (dead before sS1/sS2 are written)
    float*  sraw     = (float*) (sm);
    int*    shist    = (int*)   (sm + 32768);
    int*    scursor  = (int*)   (sm + 49152);

    const int tid  = threadIdx.x;
    const int lane = tid & 31;

    // ---- phase 1: load neg, zero hist ----
    for (int i = tid; i < BB; i += 1024)    sraw[i] = g_neg[i];
    for (int i = tid; i < NBINS; i += 1024) shist[i] = 0;
    __syncthreads();

    // ---- phase 2: histogram with warp-aggregated atomics ----
    for (int i = tid; i < BB; i += 1024) {
        int b = binOf(sraw[i]);
        unsigned mask = __match_any_sync(0xffffffffu, b);
        if (lane == (__ffs(mask) - 1)) atomicAdd(&shist[b], __popc(mask));
    }
    __syncthreads();

    // ---- phase 3: exclusive scan over 4096 bins ----
    const int tb = tid * 4;
    int tsum = shist[tb] + shist[tb + 1] + shist[tb + 2] + shist[tb + 3];
    iscan[tid] = tsum;
    __syncthreads();
    for (int off = 1; off < 1024; off <<= 1) {
        int v = (tid >= off) ? iscan[tid - off] : 0;
        __syncthreads();
        iscan[tid] += v;
        __syncthreads();
    }
    {
        int ex = iscan[tid] - tsum;
#pragma unroll
        for (int k = 0; k < 4; k++) {
            sbinStart[tb + k] = ex;
            scursor[tb + k]   = ex;
            ex += shist[tb + k];
        }
        if (tid == 1023) sbinStart[NBINS] = ex;   // = BB
    }
    __syncthreads();

    // ---- phase 4: scatter into bin-grouped order (warp-aggregated) ----
    for (int i = tid; i < BB; i += 1024) {
        float v = sraw[i];
        int b = binOf(v);
        unsigned mask = __match_any_sync(0xffffffffu, b);
        int leader = __ffs(mask) - 1;
        int pos0 = 0;
        if (lane == leader) pos0 = atomicAdd(&scursor[b], __popc(mask));
        pos0 = __shfl_sync(0xffffffffu, pos0, leader);
        ssorted[pos0 + __popc(mask & ((1u << lane) - 1u))] = v;
    }
    __syncthreads();   // sraw/shist/scursor dead from here

    // ---- phase 5: element-level suffix sums (double) over sorted ----
    const int base8 = tid * 8;
    double tl1[8], tl2[8];
    double a1 = 0.0, a2 = 0.0;
#pragma unroll
    for (int k = 7; k >= 0; --k) {
        float n = ssorted[base8 + k];
        a1 += (double)n;
        a2 += (double)n * (double)n;
        tl1[k] = a1; tl2[k] = a2;
    }
    p1[tid] = a1; p2[tid] = a2;
    __syncthreads();
    for (int off = 1; off < 1024; off <<= 1) {
        double v1 = (tid + off < 1024) ? p1[tid + off] : 0.0;
        double v2 = (tid + off < 1024) ? p2[tid + off] : 0.0;
        __syncthreads();
        p1[tid] += v1; p2[tid] += v2;
        __syncthreads();
    }
    {
        double o1 = p1[tid] - a1, o2 = p2[tid] - a2;
#pragma unroll
        for (int k = 0; k < 8; k++) {
            sS1[base8 + k] = tl1[k] + o1;
            sS2[base8 + k] = tl2[k] + o2;
        }
        if (tid == 0) { sS1[BB] = 0.0; sS2[BB] = 0.0; }
    }
    __syncthreads();

    // ---- phase 6: queries + reduction ----
    double acc = 0.0;
    int vc = 0;
    for (int i = tid; i < BB; i += 1024) {
        float m = g_posm[i];
        if (!(m < 1.0f)) continue;       // invalid (+INF); valid m < 0.7 always
        vc++;
        long long cnt; double S1, S2;
        if (m <= 0.0f) {
            cnt = BB; S1 = sS1[0]; S2 = sS2[0];
        } else {
            int b = binOf(m); if (b > NBINS - 1) b = NBINS - 1;
            int st = sbinStart[b], en = sbinStart[b + 1];
            cnt = BB - en; S1 = sS1[en]; S2 = sS2[en];
            for (int t = st; t < en; t++) {          // exact boundary-bin scan
                float n = ssorted[t];
                if (n > m) { cnt++; S1 += (double)n; S2 += (double)n * (double)n; }
            }
        }
        double md = (double)m;
        acc += (double)cnt * md * md - 2.0 * md * S1 + S2;
    }
    __syncthreads();
    p1[tid] = acc; iscan[tid] = vc;
    __syncthreads();
    for (int s = 512; s; s >>= 1) {
        if (tid < s) { p1[tid] += p1[tid + s]; iscan[tid] += iscan[tid + s]; }
        __syncthreads();
    }
    if (tid == 0) {
        double p = (double)iscan[0];
        out[0] = (float)(p1[0] / (p + 1.0) / ((double)BB + 1.0));
    }
}

// ---------------- launch ----------------
extern "C" void kernel_launch(void* const* d_in, const int* in_sizes, int n_in,
                              void* d_out, int out_size) {
    const float* x = (const float*)d_in[0];
    const void*  y = d_in[1];

    k_detect<<<1, 1024>>>((const int4*)y);
    k_row<<<BB, 128>>>(x, y);
    cudaFuncSetAttribute(k_main, cudaFuncAttributeMaxDynamicSharedMemorySize, K2_SMEM);
    k_main<<<1, 1024, K2_SMEM>>>((float*)d_out);
}